// round 16
// baseline (speedup 1.0000x reference)
#include <cuda_runtime.h>
#include <cuda_bf16.h>
#include <mma.h>
#include <cstdint>

using namespace nvcuda;

#define NN 50000
#define EE 800000
#define CC 64
#define BN_EPS 1e-5f

#define NODE_BLOCKS 1563          // ceil(50000/32)

// ---------------- scratch (static __device__ globals; no allocation) ----------------
static __device__ __align__(16) float g_P[NN * CC];      // x @ W0[:64]
static __device__ __align__(16) float g_Q[NN * CC];      // x @ W0[64:]
static __device__ __align__(16) float g_Y[EE * CC];      // sorted-order y scratch
static __device__ int   g_src[EE];
static __device__ int   g_dst[EE];
static __device__ int   g_ssrc[EE];                      // src of sorted edge
static __device__ int   g_sdst[EE];                      // dst of sorted edge
static __device__ int   g_deg[NN];
static __device__ int   g_off[NN + 1];
static __device__ int   g_cur[NN];
static __device__ int   g_eperm[EE];                     // sorted pos -> original edge id
static __device__ __align__(16) float g_sum[3][CC];
static __device__ __align__(16) float g_sq[3][CC];
static __device__ int   g_is64;
// bf16 hi/lo split of W1/W2 (row-major [k][n])
static __device__ __align__(16) __nv_bfloat16 g_Whi[2][4096];
static __device__ __align__(16) __nv_bfloat16 g_Wlo[2][4096];

// ---------------- smem layout for wmma layer kernel (bytes) ----------------
#define ROWS 256
#define LDA 72
#define LDB 72
#define LDS_F 68
#define O_AHI 0
#define O_ALO 36864     // 256*72*2
#define O_BHI 73728
#define O_BLO 82944
#define O_BN  92160     // 64 floats bnA + 64 floats bnB
#define SMEM_LK 92672

// ---------------- prologue kernels ----------------

// zero scratch; block 0 detects int64 vs int32; blocks 1,2 do the W hi/lo split.
__global__ void k_zero(const unsigned* __restrict__ w,
                       const float* __restrict__ W1,
                       const float* __restrict__ W2) {
    int i = blockIdx.x * 256 + threadIdx.x;
    if (i < NN) g_deg[i] = 0;
    if (i < 3 * CC) {
        ((float*)g_sum)[i] = 0.0f;
        ((float*)g_sq)[i] = 0.0f;
    }
    if (blockIdx.x == 0) {
        __shared__ int bad;
        if (threadIdx.x == 0) bad = 0;
        __syncthreads();
        int b = 0;
        for (int j = threadIdx.x; j < 1024; j += 256)
            if (w[2 * j + 1] != 0u) b = 1;
        if (b) atomicOr(&bad, 1);
        __syncthreads();
        if (threadIdx.x == 0) g_is64 = bad ? 0 : 1;
    } else if (blockIdx.x <= 2) {
        int which = blockIdx.x - 1;
        const float* W = (which == 0) ? W1 : W2;
        for (int idx = threadIdx.x; idx < 4096; idx += 256) {
            float v = W[idx];
            __nv_bfloat16 hi = __float2bfloat16(v);
            __nv_bfloat16 lo = __float2bfloat16(v - __bfloat162float(hi));
            g_Whi[which][idx] = hi;
            g_Wlo[which][idx] = lo;
        }
    }
}

__global__ void k_convert(const void* __restrict__ ei) {
    int e = blockIdx.x * 256 + threadIdx.x;
    if (e >= EE) return;
    int s, d;
    if (g_is64) {
        const long long* p = (const long long*)ei;
        s = (int)p[e];
        d = (int)p[EE + e];
    } else {
        const int* p = (const int*)ei;
        s = p[e];
        d = p[EE + e];
    }
    g_src[e] = s;
    g_dst[e] = d;
    atomicAdd(&g_deg[d], 1);
}

// Node-level GEMM: P = x @ W0[:64], Q = x @ W0[64:].
// Extra block (== NODE_BLOCKS) runs the degree scan, hidden under the GEMM wave.
__global__ void __launch_bounds__(256) k_node(const float* __restrict__ x,
                                              const float* __restrict__ W0) {
    __shared__ float sW[64][128];
    __shared__ float sx[32][64];
    int t = threadIdx.x;

    if (blockIdx.x == NODE_BLOCKS) {
        __shared__ int part[256];
        const int CH = (NN + 255) / 256;   // 196
        int base = t * CH;
        int s = 0;
        for (int j = 0; j < CH; j++) {
            int n = base + j;
            if (n < NN) s += g_deg[n];
        }
        part[t] = s;
        __syncthreads();
        for (int off = 1; off < 256; off <<= 1) {
            int v = (t >= off) ? part[t - off] : 0;
            __syncthreads();
            part[t] += v;
            __syncthreads();
        }
        int run = part[t] - s;
        for (int j = 0; j < CH; j++) {
            int n = base + j;
            if (n < NN) {
                g_off[n] = run;
                g_cur[n] = run;
                run += g_deg[n];
            }
        }
        if (t == 255) g_off[NN] = EE;
        return;
    }

#pragma unroll
    for (int i = 0; i < 32; i++) {
        int idx = t + i * 256;
        int k = idx >> 7;
        int cc = idx & 127;
        sW[k][cc] = (cc < 64) ? W0[k * 64 + cc] : W0[(64 + k) * 64 + (cc - 64)];
    }
    int n0 = blockIdx.x * 32;
#pragma unroll
    for (int i = 0; i < 8; i++) {
        int idx = t + i * 256;
        int nl = idx >> 6;
        int k = idx & 63;
        int n = n0 + nl;
        sx[nl][k] = (n < NN) ? x[n * 64 + k] : 0.0f;
    }
    __syncthreads();
    int tc = t & 31;
    int tn = t >> 5;
    float acc[4][4] = {};
#pragma unroll 16
    for (int k = 0; k < 64; k++) {
        float4 w = *(const float4*)&sW[k][tc * 4];
        float x0 = sx[tn * 4 + 0][k];
        float x1 = sx[tn * 4 + 1][k];
        float x2 = sx[tn * 4 + 2][k];
        float x3 = sx[tn * 4 + 3][k];
        acc[0][0] = fmaf(x0, w.x, acc[0][0]); acc[0][1] = fmaf(x0, w.y, acc[0][1]);
        acc[0][2] = fmaf(x0, w.z, acc[0][2]); acc[0][3] = fmaf(x0, w.w, acc[0][3]);
        acc[1][0] = fmaf(x1, w.x, acc[1][0]); acc[1][1] = fmaf(x1, w.y, acc[1][1]);
        acc[1][2] = fmaf(x1, w.z, acc[1][2]); acc[1][3] = fmaf(x1, w.w, acc[1][3]);
        acc[2][0] = fmaf(x2, w.x, acc[2][0]); acc[2][1] = fmaf(x2, w.y, acc[2][1]);
        acc[2][2] = fmaf(x2, w.z, acc[2][2]); acc[2][3] = fmaf(x2, w.w, acc[2][3]);
        acc[3][0] = fmaf(x3, w.x, acc[3][0]); acc[3][1] = fmaf(x3, w.y, acc[3][1]);
        acc[3][2] = fmaf(x3, w.z, acc[3][2]); acc[3][3] = fmaf(x3, w.w, acc[3][3]);
    }
#pragma unroll
    for (int i = 0; i < 4; i++) {
        int n = n0 + tn * 4 + i;
        if (n < NN) {
            float4 v = make_float4(acc[i][0], acc[i][1], acc[i][2], acc[i][3]);
            if (tc < 16)
                *(float4*)&g_P[n * 64 + tc * 4] = v;
            else
                *(float4*)&g_Q[n * 64 + (tc - 16) * 4] = v;
        }
    }
}

__global__ void k_sortE() {
    int e = blockIdx.x * 256 + threadIdx.x;
    if (e >= EE) return;
    int s = g_src[e];
    int d = g_dst[e];
    int pos = atomicAdd(&g_cur[d], 1);
    g_eperm[pos] = e;
    g_ssrc[pos] = s;
    g_sdst[pos] = d;
}

// Layer-0 stats over sorted pairs; 2-edge manual unroll for deeper MLP.
__global__ void k_stats0() {
    __shared__ float ss[CC], sq[CC];
    int t = threadIdx.x;
    if (t < CC) { ss[t] = 0.0f; sq[t] = 0.0f; }
    __syncthreads();
    int lane = t & 31;
    int warp = (blockIdx.x * 256 + t) >> 5;
    int nw = (gridDim.x * 256) >> 5;
    float2 s = make_float2(0.0f, 0.0f), q = make_float2(0.0f, 0.0f);
    int e = warp;
    for (; e + nw < EE; e += 2 * nw) {
        int dA = g_sdst[e],      sA = g_ssrc[e];
        int dB = g_sdst[e + nw], sB = g_ssrc[e + nw];
        float2 pA = *(const float2*)&g_P[dA * CC + 2 * lane];
        float2 qA = *(const float2*)&g_Q[sA * CC + 2 * lane];
        float2 pB = *(const float2*)&g_P[dB * CC + 2 * lane];
        float2 qB = *(const float2*)&g_Q[sB * CC + 2 * lane];
        float a0 = pA.x + qA.x, a1 = pA.y + qA.y;
        float b0 = pB.x + qB.x, b1 = pB.y + qB.y;
        s.x += a0 + b0; s.y += a1 + b1;
        q.x = fmaf(a0, a0, fmaf(b0, b0, q.x));
        q.y = fmaf(a1, a1, fmaf(b1, b1, q.y));
    }
    for (; e < EE; e += nw) {
        int dst = g_sdst[e], src = g_ssrc[e];
        float2 p = *(const float2*)&g_P[dst * CC + 2 * lane];
        float2 qq = *(const float2*)&g_Q[src * CC + 2 * lane];
        float y0 = p.x + qq.x, y1 = p.y + qq.y;
        s.x += y0; s.y += y1;
        q.x = fmaf(y0, y0, q.x); q.y = fmaf(y1, y1, q.y);
    }
    atomicAdd(&ss[2 * lane], s.x);
    atomicAdd(&ss[2 * lane + 1], s.y);
    atomicAdd(&sq[2 * lane], q.x);
    atomicAdd(&sq[2 * lane + 1], q.y);
    __syncthreads();
    if (t < CC) {
        atomicAdd(&g_sum[0][t], ss[t]);
        atomicAdd(&g_sq[0][t], sq[t]);
    }
}

// ---------------- WMMA edge layer: 256-edge tile, sorted-position order ----------------
// mode 0: A = BN0+ReLU(P[sdst]+Q[ssrc]), B = W1, g_Y[pos] = y1, stats -> 1
// mode 1: A = BN1+ReLU(g_Y[pos]),        B = W2, g_Y[pos] = y2, stats -> 2
// BN constants computed per block (finalize inlined).
__global__ void __launch_bounds__(256, 2) k_layerT(int mode,
                                                   const float* __restrict__ gam,
                                                   const float* __restrict__ bet) {
    extern __shared__ char smem[];
    __nv_bfloat16* A_hi = (__nv_bfloat16*)(smem + O_AHI);
    __nv_bfloat16* A_lo = (__nv_bfloat16*)(smem + O_ALO);
    __nv_bfloat16* B_hi = (__nv_bfloat16*)(smem + O_BHI);
    __nv_bfloat16* B_lo = (__nv_bfloat16*)(smem + O_BLO);
    float* sBnA = (float*)(smem + O_BN);
    float* sBnB = sBnA + CC;
    float* stage = (float*)smem;   // aliases A region after the post-GEMM barrier
    int t = threadIdx.x;
    int L = mode;

    if (t < CC) {
        float inv = 1.0f / (float)EE;
        float m = g_sum[L][t] * inv;
        float v = g_sq[L][t] * inv - m * m;
        float a = gam[t] * rsqrtf(v + BN_EPS);
        sBnA[t] = a;
        sBnB[t] = bet[t] - m * a;
    }

    int e0 = blockIdx.x * ROWS;
    int pos = e0 + t;
    const float* src0;
    const float* src1 = nullptr;
    if (mode == 0) {
        int nd = g_sdst[pos];
        int ns = g_ssrc[pos];
        src0 = &g_P[(size_t)nd * CC];
        src1 = &g_Q[(size_t)ns * CC];
    } else {
        src0 = &g_Y[(size_t)pos * CC];
    }

    {
        const uint32_t* wh = (const uint32_t*)&g_Whi[mode][0];
        const uint32_t* wl = (const uint32_t*)&g_Wlo[mode][0];
#pragma unroll
        for (int i = 0; i < 8; i++) {
            int idx2 = t + i * 256;
            int k = idx2 >> 5, n2 = idx2 & 31;
            ((uint32_t*)(B_hi + k * LDB))[n2] = wh[idx2];
            ((uint32_t*)(B_lo + k * LDB))[n2] = wl[idx2];
        }
    }
    __syncthreads();

#pragma unroll
    for (int i = 0; i < 8; i++) {
        int c = i * 8;
        float4 a0 = *(const float4*)&src0[c];
        float4 a1 = *(const float4*)&src0[c + 4];
        if (mode == 0) {
            float4 b0 = *(const float4*)&src1[c];
            float4 b1 = *(const float4*)&src1[c + 4];
            a0.x += b0.x; a0.y += b0.y; a0.z += b0.z; a0.w += b0.w;
            a1.x += b1.x; a1.y += b1.y; a1.z += b1.z; a1.w += b1.w;
        }
        float v[8] = {a0.x, a0.y, a0.z, a0.w, a1.x, a1.y, a1.z, a1.w};
        float4 A0 = *(const float4*)&sBnA[c];
        float4 A1 = *(const float4*)&sBnA[c + 4];
        float4 B0 = *(const float4*)&sBnB[c];
        float4 B1 = *(const float4*)&sBnB[c + 4];
        float bnA[8] = {A0.x, A0.y, A0.z, A0.w, A1.x, A1.y, A1.z, A1.w};
        float bnB[8] = {B0.x, B0.y, B0.z, B0.w, B1.x, B1.y, B1.z, B1.w};
        uint32_t hw[4], lw[4];
#pragma unroll
        for (int j = 0; j < 4; j++) {
            float x0 = fmaxf(fmaf(bnA[2 * j],     v[2 * j],     bnB[2 * j]),     0.0f);
            float x1 = fmaxf(fmaf(bnA[2 * j + 1], v[2 * j + 1], bnB[2 * j + 1]), 0.0f);
            __nv_bfloat16 h0 = __float2bfloat16(x0);
            __nv_bfloat16 h1 = __float2bfloat16(x1);
            __nv_bfloat16 l0 = __float2bfloat16(x0 - __bfloat162float(h0));
            __nv_bfloat16 l1 = __float2bfloat16(x1 - __bfloat162float(h1));
            hw[j] = (uint32_t)__bfloat16_as_ushort(h0) |
                    ((uint32_t)__bfloat16_as_ushort(h1) << 16);
            lw[j] = (uint32_t)__bfloat16_as_ushort(l0) |
                    ((uint32_t)__bfloat16_as_ushort(l1) << 16);
        }
        *(uint4*)&A_hi[t * LDA + c] = make_uint4(hw[0], hw[1], hw[2], hw[3]);
        *(uint4*)&A_lo[t * LDA + c] = make_uint4(lw[0], lw[1], lw[2], lw[3]);
    }
    __syncthreads();

    int w = t >> 5;
    wmma::fragment<wmma::accumulator, 16, 16, 16, float> acc0[4], acc1[4];
#pragma unroll
    for (int j = 0; j < 4; j++) {
        wmma::fill_fragment(acc0[j], 0.0f);
        wmma::fill_fragment(acc1[j], 0.0f);
    }
    int row0 = w * 32;
#pragma unroll
    for (int k0 = 0; k0 < 64; k0 += 16) {
        wmma::fragment<wmma::matrix_a, 16, 16, 16, __nv_bfloat16, wmma::row_major> ah0, al0, ah1, al1;
        wmma::load_matrix_sync(ah0, A_hi + row0 * LDA + k0, LDA);
        wmma::load_matrix_sync(al0, A_lo + row0 * LDA + k0, LDA);
        wmma::load_matrix_sync(ah1, A_hi + (row0 + 16) * LDA + k0, LDA);
        wmma::load_matrix_sync(al1, A_lo + (row0 + 16) * LDA + k0, LDA);
#pragma unroll
        for (int j = 0; j < 4; j++) {
            wmma::fragment<wmma::matrix_b, 16, 16, 16, __nv_bfloat16, wmma::row_major> bh, bl;
            wmma::load_matrix_sync(bh, B_hi + k0 * LDB + j * 16, LDB);
            wmma::load_matrix_sync(bl, B_lo + k0 * LDB + j * 16, LDB);
            wmma::mma_sync(acc0[j], ah0, bh, acc0[j]);
            wmma::mma_sync(acc0[j], al0, bh, acc0[j]);
            wmma::mma_sync(acc0[j], ah0, bl, acc0[j]);
            wmma::mma_sync(acc1[j], ah1, bh, acc1[j]);
            wmma::mma_sync(acc1[j], al1, bh, acc1[j]);
            wmma::mma_sync(acc1[j], ah1, bl, acc1[j]);
        }
    }
    __syncthreads();
#pragma unroll
    for (int j = 0; j < 4; j++) {
        wmma::store_matrix_sync(stage + row0 * LDS_F + j * 16, acc0[j], LDS_F,
                                wmma::mem_row_major);
        wmma::store_matrix_sync(stage + (row0 + 16) * LDS_F + j * 16, acc1[j], LDS_F,
                                wmma::mem_row_major);
    }
    __syncthreads();

    int SL = (mode == 0) ? 1 : 2;
    {
        int c = t & 63, quarter = t >> 6;
        float s = 0.0f, q = 0.0f;
#pragma unroll 8
        for (int rr = 0; rr < 64; rr++) {
            float vv = stage[(quarter * 64 + rr) * LDS_F + c];
            s += vv;
            q = fmaf(vv, vv, q);
        }
        atomicAdd(&g_sum[SL][c], s);
        atomicAdd(&g_sq[SL][c], q);
    }

    float* dst = g_Y + (size_t)e0 * CC;
#pragma unroll
    for (int j2 = 0; j2 < 16; j2++) {
        int f = j2 * 1024 + t * 4;
        int rr = f >> 6, cc2 = f & 63;
        uint4 v = *(const uint4*)&stage[rr * LDS_F + cc2];
        *(uint4*)&dst[f] = v;
    }
}

// Segmented mean: warp per node, 2 edges per iteration (half-warps), float4
// lanes -> 4 rows in flight with unroll 2. BN2 inlined. No atomics.
__global__ void __launch_bounds__(256) k_agg(float* __restrict__ out,
                                             const float* __restrict__ gam,
                                             const float* __restrict__ bet) {
    int wid = (blockIdx.x * 256 + threadIdx.x) >> 5;
    int lane = threadIdx.x & 31;
    if (wid >= NN) return;
    int half = lane >> 4;          // 0 or 1
    int li = lane & 15;            // lane within half: cols [li*4, li*4+4)
    int c = li * 4;

    float inv = 1.0f / (float)EE;
    float4 sA, sB;
    {
        float4 gs = *(const float4*)&g_sum[2][c];
        float4 gq = *(const float4*)&g_sq[2][c];
        float4 gm = *(const float4*)&gam[c];
        float4 bt = *(const float4*)&bet[c];
        float m0 = gs.x * inv, m1 = gs.y * inv, m2 = gs.z * inv, m3 = gs.w * inv;
        sA.x = gm.x * rsqrtf(gq.x * inv - m0 * m0 + BN_EPS);
        sA.y = gm.y * rsqrtf(gq.y * inv - m1 * m1 + BN_EPS);
        sA.z = gm.z * rsqrtf(gq.z * inv - m2 * m2 + BN_EPS);
        sA.w = gm.w * rsqrtf(gq.w * inv - m3 * m3 + BN_EPS);
        sB.x = bt.x - m0 * sA.x;
        sB.y = bt.y - m1 * sA.y;
        sB.z = bt.z - m2 * sA.z;
        sB.w = bt.w - m3 * sA.w;
    }

    int start = g_off[wid], end = g_off[wid + 1];
    float4 acc = make_float4(0.0f, 0.0f, 0.0f, 0.0f);
    float* oe = out + (size_t)NN * CC;
#pragma unroll 2
    for (int j = start; j < end; j += 2) {
        int e = j + half;
        if (e < end) {
            float4 v = *(const float4*)&g_Y[(size_t)e * CC + c];
            v.x = fmaxf(fmaf(sA.x, v.x, sB.x), 0.0f);
            v.y = fmaxf(fmaf(sA.y, v.y, sB.y), 0.0f);
            v.z = fmaxf(fmaf(sA.z, v.z, sB.z), 0.0f);
            v.w = fmaxf(fmaf(sA.w, v.w, sB.w), 0.0f);
            int eid = g_eperm[e];
            *(float4*)&oe[(size_t)eid * CC + c] = v;
            acc.x += v.x; acc.y += v.y; acc.z += v.z; acc.w += v.w;
        }
    }
    // combine the two half-warps' partial sums (same columns, different edges)
    acc.x += __shfl_xor_sync(0xffffffffu, acc.x, 16);
    acc.y += __shfl_xor_sync(0xffffffffu, acc.y, 16);
    acc.z += __shfl_xor_sync(0xffffffffu, acc.z, 16);
    acc.w += __shfl_xor_sync(0xffffffffu, acc.w, 16);
    if (half == 0) {
        float d = fmaxf((float)(end - start), 1.0f);
        *(float4*)&out[(size_t)wid * CC + c] =
            make_float4(acc.x / d, acc.y / d, acc.z / d, acc.w / d);
    }
}

extern "C" void kernel_launch(void* const* d_in, const int* in_sizes, int n_in,
                              void* d_out, int out_size) {
    const float* x = (const float*)d_in[0];
    const void* ei = d_in[1];
    const float* W0 = (const float*)d_in[2];
    const float* g0 = (const float*)d_in[4];
    const float* be0 = (const float*)d_in[5];
    const float* W1 = (const float*)d_in[6];
    const float* g1 = (const float*)d_in[8];
    const float* be1 = (const float*)d_in[9];
    const float* W2 = (const float*)d_in[10];
    const float* g2 = (const float*)d_in[12];
    const float* be2 = (const float*)d_in[13];
    float* out = (float*)d_out;

    static int s_attr_done = 0;
    if (!s_attr_done) {
        cudaFuncSetAttribute(k_layerT, cudaFuncAttributeMaxDynamicSharedMemorySize, SMEM_LK);
        s_attr_done = 1;
    }

    k_zero<<<(NN + 255) / 256, 256>>>((const unsigned*)ei, W1, W2);
    k_convert<<<(EE + 255) / 256, 256>>>(ei);
    k_node<<<NODE_BLOCKS + 1, 256>>>(x, W0);
    k_sortE<<<(EE + 255) / 256, 256>>>();
    k_stats0<<<2048, 256>>>();
    k_layerT<<<EE / ROWS, 256, SMEM_LK>>>(0, g0, be0);
    k_layerT<<<EE / ROWS, 256, SMEM_LK>>>(1, g1, be1);
    k_agg<<<(NN * 32 + 255) / 256, 256>>>(out, g2, be2);
}